// round 9
// baseline (speedup 1.0000x reference)
#include <cuda_runtime.h>
#include <cuda_bf16.h>
#include <math.h>
#include <cstdint>

// ---------------------------------------------------------------------------
// PhysicsGuidedAttentionCorrected
// B=8, N=1024, C=256, NUM_HEADS=8, hd=32
// R9: attention processes 128-key super-tiles (one sync per 2 key tiles),
//     log2-domain softmax (bias pre-scaled by log2e, exp2f), wind fused
//     into convert kernel. GEMMs as R8.
// ---------------------------------------------------------------------------

#define B_ 8
#define N_ 1024
#define C_ 256
#define NH_ 8
#define HD_ 32

#define LOG2E 1.4426950408889634f

// scratch (device globals; no allocations allowed)
__device__ float g_ws[B_ * N_];
__device__ float4 g_bias4[B_ * N_ * N_ / 4];       // fragment-ordered, ×log2e
__device__ __nv_bfloat16 g_xh[B_ * N_ * C_];
__device__ __nv_bfloat16 g_xl[B_ * N_ * C_];
__device__ __nv_bfloat16 g_wqkvh[3 * C_ * C_];
__device__ __nv_bfloat16 g_wqkvl[3 * C_ * C_];
__device__ __nv_bfloat16 g_wprojh[C_ * C_];
__device__ __nv_bfloat16 g_wprojl[C_ * C_];
__device__ __nv_bfloat16 g_qkvh[B_ * N_ * 3 * C_];
__device__ __nv_bfloat16 g_qkvl[B_ * N_ * 3 * C_];
__device__ __nv_bfloat16 g_attnh[B_ * N_ * C_];
__device__ __nv_bfloat16 g_attnl[B_ * N_ * C_];

// ---------------------------------------------------------------------------
// helpers
// ---------------------------------------------------------------------------
__device__ __forceinline__ uint32_t smem_u32(const void* p) {
    uint32_t a;
    asm("{ .reg .u64 t; cvta.to.shared.u64 t, %1; cvt.u32.u64 %0, t; }"
        : "=r"(a) : "l"(p));
    return a;
}

#define LDSM_X4(r0, r1, r2, r3, addr)                                        \
    asm volatile("ldmatrix.sync.aligned.m8n8.x4.shared.b16 {%0,%1,%2,%3}, [%4];" \
                 : "=r"(r0), "=r"(r1), "=r"(r2), "=r"(r3) : "r"(addr))

#define LDSM_X4T(r0, r1, r2, r3, addr)                                       \
    asm volatile("ldmatrix.sync.aligned.m8n8.x4.trans.shared.b16 {%0,%1,%2,%3}, [%4];" \
                 : "=r"(r0), "=r"(r1), "=r"(r2), "=r"(r3) : "r"(addr))

#define MMA_BF16(d, a0, a1, a2, a3, b0, b1)                                  \
    asm volatile("mma.sync.aligned.m16n8k16.row.col.f32.bf16.bf16.f32 "      \
                 "{%0,%1,%2,%3}, {%4,%5,%6,%7}, {%8,%9}, {%0,%1,%2,%3};"     \
                 : "+f"((d)[0]), "+f"((d)[1]), "+f"((d)[2]), "+f"((d)[3])    \
                 : "r"(a0), "r"(a1), "r"(a2), "r"(a3), "r"(b0), "r"(b1))

#define CP_ASYNC16(saddr, gptr)                                              \
    asm volatile("cp.async.cg.shared.global [%0], [%1], 16;"                 \
                 :: "r"(saddr), "l"(gptr))
#define CP_COMMIT() asm volatile("cp.async.commit_group;" ::: "memory")
#define CP_WAIT0()  asm volatile("cp.async.wait_group 0;" ::: "memory")

__device__ __forceinline__ void split2(float x, float y,
                                       __nv_bfloat162& hi, __nv_bfloat162& lo) {
    __nv_bfloat16 hx = __float2bfloat16_rn(x);
    __nv_bfloat16 hy = __float2bfloat16_rn(y);
    hi = __nv_bfloat162(hx, hy);
    lo = __nv_bfloat162(__float2bfloat16_rn(x - __bfloat162float(hx)),
                        __float2bfloat16_rn(y - __bfloat162float(hy)));
}
__device__ __forceinline__ uint32_t u32of(__nv_bfloat162 v) {
    return *reinterpret_cast<uint32_t*>(&v);
}

// ---------------------------------------------------------------------------
// bias precompute in MMA-fragment order, pre-multiplied by log2e.
// ---------------------------------------------------------------------------
__device__ __forceinline__ float bias_val(float ei, float wi, float ej,
                                          float wj, float alpha, float beta) {
    float ed = fmaxf((ej - ei) * 1e-3f, 0.0f);
    float z = (wi + wj) * 0.5f - 5.0f;
    float wf = 1.0f / (1.0f + __expf(-z));
    float bia = -alpha * ed * (1.0f - beta * wf);
    return fminf(fmaxf(bia, -10.0f), 0.0f) * LOG2E;
}

__global__ __launch_bounds__(256)
void bias_perm_kernel(const float* __restrict__ elev, const float* __restrict__ ws,
                      const float* __restrict__ alpha_p,
                      const float* __restrict__ beta_p,
                      float4* __restrict__ bias4) {
    const int t = blockIdx.x * blockDim.x + threadIdx.x;
    const int lane = t & 31;
    const int nt = (t >> 5) & 7;
    const int w  = (t >> 8) & 7;
    const int kt = (t >> 11) & 15;
    const int qt = (t >> 15) & 7;
    const int b  = t >> 18;
    const float alpha = *alpha_p;
    const float beta = *beta_p;

    const int i0 = qt * 128 + w * 16 + (lane >> 2);
    const int j0 = kt * 64 + nt * 8 + 2 * (lane & 3);
    const float* e = elev + b * 1024;
    const float* wsb = ws + b * 1024;
    float ei0 = e[i0], ei1 = e[i0 + 8];
    float wi0 = wsb[i0], wi1 = wsb[i0 + 8];
    float ej0 = e[j0], ej1 = e[j0 + 1];
    float wj0 = wsb[j0], wj1 = wsb[j0 + 1];

    float4 o;
    o.x = bias_val(ei0, wi0, ej0, wj0, alpha, beta);
    o.y = bias_val(ei0, wi0, ej1, wj1, alpha, beta);
    o.z = bias_val(ei1, wi1, ej0, wj0, alpha, beta);
    o.w = bias_val(ei1, wi1, ej1, wj1, alpha, beta);
    bias4[t] = o;
}

// ---------------------------------------------------------------------------
// merged converter (x | wqkv | wproj) + fused wind strength
// ---------------------------------------------------------------------------
#define N4_X (B_ * N_ * C_ / 4)
#define N4_WQKV (3 * C_ * C_ / 4)
#define N4_WPROJ (C_ * C_ / 4)
#define N4_TOTAL (N4_X + N4_WQKV + N4_WPROJ)

__global__ void convert_all(const float* __restrict__ x,
                            const float* __restrict__ wqkv,
                            const float* __restrict__ wproj,
                            const float* __restrict__ uwind,
                            const float* __restrict__ vwind,
                            __nv_bfloat16* __restrict__ xh, __nv_bfloat16* __restrict__ xl,
                            __nv_bfloat16* __restrict__ wqh, __nv_bfloat16* __restrict__ wql,
                            __nv_bfloat16* __restrict__ wph, __nv_bfloat16* __restrict__ wpl,
                            float* __restrict__ ws) {
    int i = blockIdx.x * blockDim.x + threadIdx.x;
    if (i >= N4_TOTAL) {
        int t = i - N4_TOTAL;
        if (t >= B_ * N_) return;
        int b = t >> 10;
        int n = t & 1023;
        int r = n >> 5;
        int c = n & 31;
        const float* ub = uwind + b * 4096;
        const float* vb = vwind + b * 4096;
        float s = 0.0f;
#pragma unroll
        for (int dr = 0; dr < 2; ++dr)
#pragma unroll
            for (int dc = 0; dc < 2; ++dc) {
                int idx = (2 * r + dr) * 64 + (2 * c + dc);
                float uu = ub[idx], vv = vb[idx];
                s += sqrtf(uu * uu + vv * vv + 1e-8f);
            }
        ws[t] = s * 0.25f;
        return;
    }
    const float* in;
    __nv_bfloat16 *hi, *lo;
    int off;
    if (i < N4_X) { in = x; hi = xh; lo = xl; off = i; }
    else if (i < N4_X + N4_WQKV) { in = wqkv; hi = wqh; lo = wql; off = i - N4_X; }
    else { in = wproj; hi = wph; lo = wpl; off = i - N4_X - N4_WQKV; }
    float4 v = reinterpret_cast<const float4*>(in)[off];
    __nv_bfloat162 h01, l01, h23, l23;
    split2(v.x, v.y, h01, l01);
    split2(v.z, v.w, h23, l23);
    uint2 hv = make_uint2(u32of(h01), u32of(h23));
    uint2 lv = make_uint2(u32of(l01), u32of(l23));
    *reinterpret_cast<uint2*>(hi + 4 * off) = hv;
    *reinterpret_cast<uint2*>(lo + 4 * off) = lv;
}

// ---------------------------------------------------------------------------
// bf16-split tensor-core GEMM, cp.async double-buffered (R7/R8, proven).
// ---------------------------------------------------------------------------
#define PITCH 40
#define GEMM_BUF_BYTES (4 * 128 * PITCH * 2)
#define GEMM_SMEM_BYTES (2 * GEMM_BUF_BYTES)

template <bool HAS_BIAS, bool SPLIT_OUT>
__global__ __launch_bounds__(256, 2)
void gemm_bs(const __nv_bfloat16* __restrict__ Ah, const __nv_bfloat16* __restrict__ Al,
             const __nv_bfloat16* __restrict__ Bh, const __nv_bfloat16* __restrict__ Bl,
             const float* __restrict__ bias, float* __restrict__ C,
             __nv_bfloat16* __restrict__ Ch, __nv_bfloat16* __restrict__ Cl, int N) {
    extern __shared__ __align__(16) char smem_raw[];
    const uint32_t uS = smem_u32(smem_raw);

    const int tid = threadIdx.x;
    const int lane = tid & 31;
    const int wid = tid >> 5;
    const int wm = wid & 1;
    const int wn = wid >> 1;
    const int bx = blockIdx.x;
    const int by = blockIdx.y;

    const __nv_bfloat16* Agh = Ah + (size_t)by * 128 * 256;
    const __nv_bfloat16* Agl = Al + (size_t)by * 128 * 256;
    const __nv_bfloat16* Bgh = Bh + (size_t)bx * 128 * 256;
    const __nv_bfloat16* Bgl = Bl + (size_t)bx * 128 * 256;

    float acc[4][4][4];
#pragma unroll
    for (int mt = 0; mt < 4; ++mt)
#pragma unroll
        for (int nt = 0; nt < 4; ++nt)
#pragma unroll
            for (int i = 0; i < 4; ++i) acc[mt][nt][i] = 0.0f;

    const uint32_t aoff =
        (uint32_t)((wm * 64 + (lane & 15)) * PITCH + ((lane & 16) ? 8 : 0)) * 2;
    const uint32_t boff =
        (uint32_t)((wn * 32 + (lane & 7) + ((lane & 16) ? 8 : 0)) * PITCH +
                   ((lane & 8) ? 8 : 0)) * 2;

    const int row0 = tid >> 2;
    const int c8 = (tid & 3) * 8;

#pragma unroll
    for (int i = 0; i < 2; ++i) {
        int row = row0 + i * 64;
        size_t g = (size_t)row * 256 + c8;
        uint32_t so = (uint32_t)(row * PITCH + c8) * 2;
        CP_ASYNC16(uS + so, Agh + g);
        CP_ASYNC16(uS + 10240 + so, Agl + g);
        CP_ASYNC16(uS + 20480 + so, Bgh + g);
        CP_ASYNC16(uS + 30720 + so, Bgl + g);
    }
    CP_COMMIT();
    CP_WAIT0();
    __syncthreads();

#pragma unroll 1
    for (int kb = 0; kb < 8; ++kb) {
        const int p = kb & 1;
        const uint32_t bufb = uS + (uint32_t)p * GEMM_BUF_BYTES;

        if (kb < 7) {
            const uint32_t nb = uS + (uint32_t)(1 - p) * GEMM_BUF_BYTES;
#pragma unroll
            for (int i = 0; i < 2; ++i) {
                int row = row0 + i * 64;
                size_t g = (size_t)row * 256 + (kb + 1) * 32 + c8;
                uint32_t so = (uint32_t)(row * PITCH + c8) * 2;
                CP_ASYNC16(nb + so, Agh + g);
                CP_ASYNC16(nb + 10240 + so, Agl + g);
                CP_ASYNC16(nb + 20480 + so, Bgh + g);
                CP_ASYNC16(nb + 30720 + so, Bgl + g);
            }
            CP_COMMIT();
        }

        const uint32_t uAh = bufb, uAl = bufb + 10240;
        const uint32_t uBh = bufb + 20480, uBl = bufb + 30720;

#pragma unroll
        for (int kk = 0; kk < 2; ++kk) {
            const uint32_t kof = (uint32_t)(kk * 16) * 2;
            uint32_t bhf[2][4], blf[2][4];
#pragma unroll
            for (int ntp = 0; ntp < 2; ++ntp) {
                uint32_t ba = boff + (uint32_t)(ntp * 16 * PITCH) * 2 + kof;
                LDSM_X4(bhf[ntp][0], bhf[ntp][1], bhf[ntp][2], bhf[ntp][3], uBh + ba);
                LDSM_X4(blf[ntp][0], blf[ntp][1], blf[ntp][2], blf[ntp][3], uBl + ba);
            }
#pragma unroll
            for (int mt = 0; mt < 4; ++mt) {
                uint32_t aa = aoff + (uint32_t)(mt * 16 * PITCH) * 2 + kof;
                uint32_t ah0, ah1, ah2, ah3, al0, al1, al2, al3;
                LDSM_X4(ah0, ah1, ah2, ah3, uAh + aa);
                LDSM_X4(al0, al1, al2, al3, uAl + aa);
#pragma unroll
                for (int nt = 0; nt < 4; ++nt) {
                    const int ntp = nt >> 1;
                    const int hb = (nt & 1) * 2;
                    MMA_BF16(acc[mt][nt], ah0, ah1, ah2, ah3,
                             bhf[ntp][hb], bhf[ntp][hb + 1]);
                    MMA_BF16(acc[mt][nt], ah0, ah1, ah2, ah3,
                             blf[ntp][hb], blf[ntp][hb + 1]);
                    MMA_BF16(acc[mt][nt], al0, al1, al2, al3,
                             bhf[ntp][hb], bhf[ntp][hb + 1]);
                }
            }
        }

        if (kb < 7) CP_WAIT0();
        __syncthreads();
    }

    const int gid = lane >> 2;
    const int tig = lane & 3;
#pragma unroll
    for (int mt = 0; mt < 4; ++mt) {
        int row = by * 128 + wm * 64 + mt * 16 + gid;
#pragma unroll
        for (int nt = 0; nt < 4; ++nt) {
            int col = bx * 128 + wn * 32 + nt * 8 + 2 * tig;
            float2 v0 = make_float2(acc[mt][nt][0], acc[mt][nt][1]);
            float2 v1 = make_float2(acc[mt][nt][2], acc[mt][nt][3]);
            if (SPLIT_OUT) {
                __nv_bfloat162 hh, ll;
                split2(v0.x, v0.y, hh, ll);
                *reinterpret_cast<uint32_t*>(Ch + (size_t)row * N + col) = u32of(hh);
                *reinterpret_cast<uint32_t*>(Cl + (size_t)row * N + col) = u32of(ll);
                split2(v1.x, v1.y, hh, ll);
                *reinterpret_cast<uint32_t*>(Ch + (size_t)(row + 8) * N + col) = u32of(hh);
                *reinterpret_cast<uint32_t*>(Cl + (size_t)(row + 8) * N + col) = u32of(ll);
            } else {
                if (HAS_BIAS) {
                    float2 bb = *reinterpret_cast<const float2*>(bias + col);
                    v0.x += bb.x; v0.y += bb.y;
                    v1.x += bb.x; v1.y += bb.y;
                }
                *reinterpret_cast<float2*>(C + (size_t)row * N + col) = v0;
                *reinterpret_cast<float2*>(C + (size_t)(row + 8) * N + col) = v1;
            }
        }
    }
}

// ---------------------------------------------------------------------------
// tensor-core flash attention: 128-key super-tiles (one cp.async wait +
// one __syncthreads per 2 key tiles), log2-domain softmax.
// ---------------------------------------------------------------------------
#define ATTN_Q_BYTES (2 * 128 * PITCH * 2)        // 20480
#define ATTN_BUF_BYTES (4 * 128 * PITCH * 2)      // 40960 per buffer (128 keys)
#define ATTN_SMEM_BYTES (ATTN_Q_BYTES + 2 * ATTN_BUF_BYTES)   // 102400

__global__ __launch_bounds__(256, 2)
void attn_mma(const __nv_bfloat16* __restrict__ qkvh,
              const __nv_bfloat16* __restrict__ qkvl,
              const float4* __restrict__ bias4,
              __nv_bfloat16* __restrict__ outh,
              __nv_bfloat16* __restrict__ outl) {
    extern __shared__ __align__(16) char smem_raw[];
    __nv_bfloat16* Qh = reinterpret_cast<__nv_bfloat16*>(smem_raw);
    __nv_bfloat16* Ql = Qh + 128 * PITCH;
    const uint32_t uQh = smem_u32(Qh);
    const uint32_t uQl = uQh + 128 * PITCH * 2;
    const uint32_t uKV = uQl + 128 * PITCH * 2;

    const int tid = threadIdx.x;
    const int lane = tid & 31;
    const int w = tid >> 5;
    const int gid = lane >> 2;
    const int tig = lane & 3;
    const int qc = blockIdx.x;
    const int h  = blockIdx.y;
    const int b  = blockIdx.z;

    // 1/sqrt(32) * log2(e)
    const float scale = 0.25505653570120927f;
    const int qrow0 = b * N_ + qc * 128;

    // prologue: stage super-tile 0 (128 keys) into buffer 0
#pragma unroll
    for (int i = 0; i < 2; ++i) {
        int slot = tid + i * 256;           // 0..511
        int row = slot >> 2;                // 0..127
        int c8 = (slot & 3) * 8;
        size_t g = (size_t)(b * N_ + row) * 768 + 256 + h * HD_ + c8;
        uint32_t so = (uint32_t)(row * PITCH + c8) * 2;
        CP_ASYNC16(uKV + so, qkvh + g);
        CP_ASYNC16(uKV + 10240 + so, qkvl + g);
        CP_ASYNC16(uKV + 20480 + so, qkvh + g + 256);
        CP_ASYNC16(uKV + 30720 + so, qkvl + g + 256);
    }
    CP_COMMIT();

    // stage Q (regular stores)
#pragma unroll
    for (int i = 0; i < 2; ++i) {
        int slot = tid + i * 256;
        int row = slot >> 2;
        int c8 = (slot & 3) * 8;
        size_t g = (size_t)(qrow0 + row) * 768 + h * HD_ + c8;
        int so = row * PITCH + c8;
        *reinterpret_cast<uint4*>(&Qh[so]) =
            *reinterpret_cast<const uint4*>(qkvh + g);
        *reinterpret_cast<uint4*>(&Ql[so]) =
            *reinterpret_cast<const uint4*>(qkvl + g);
    }
    CP_WAIT0();
    __syncthreads();

    const uint32_t aoff =
        (uint32_t)((w * 16 + (lane & 15)) * PITCH + ((lane & 16) ? 8 : 0)) * 2;
    const uint32_t koff =
        (uint32_t)(((lane & 7) + ((lane & 16) ? 8 : 0)) * PITCH +
                   ((lane & 8) ? 8 : 0)) * 2;
    const uint32_t voff =
        (uint32_t)((lane & 15) * PITCH + ((lane & 16) ? 8 : 0)) * 2;

    // hoisted Q fragments
    uint32_t qh[2][4], ql[2][4];
#pragma unroll
    for (int kk = 0; kk < 2; ++kk) {
        const uint32_t kof = (uint32_t)(kk * 16) * 2;
        LDSM_X4(qh[kk][0], qh[kk][1], qh[kk][2], qh[kk][3], uQh + aoff + kof);
        LDSM_X4(ql[kk][0], ql[kk][1], ql[kk][2], ql[kk][3], uQl + aoff + kof);
    }

    float m0 = -1e30f, m1 = -1e30f, l0 = 0.0f, l1 = 0.0f;
    float oacc[4][4];
#pragma unroll
    for (int nt = 0; nt < 4; ++nt)
#pragma unroll
        for (int i = 0; i < 4; ++i) oacc[nt][i] = 0.0f;

    const int qi0 = qc * 128 + w * 16 + gid;
    (void)qi0;
    const float4* bias_tb =
        bias4 + ((size_t)((b * 8 + qc) * 16)) * 2048 + (w * 8) * 32 + lane;

#pragma unroll 1
    for (int ko = 0; ko < 8; ++ko) {
        const int p = ko & 1;
        const uint32_t bufb = uKV + (uint32_t)p * ATTN_BUF_BYTES;

        if (ko < 7) {
            const uint32_t nb = uKV + (uint32_t)(1 - p) * ATTN_BUF_BYTES;
#pragma unroll
            for (int i = 0; i < 2; ++i) {
                int slot = tid + i * 256;
                int row = slot >> 2;
                int c8 = (slot & 3) * 8;
                size_t g = (size_t)(b * N_ + (ko + 1) * 128 + row) * 768 + 256 +
                           h * HD_ + c8;
                uint32_t so = (uint32_t)(row * PITCH + c8) * 2;
                CP_ASYNC16(nb + so, qkvh + g);
                CP_ASYNC16(nb + 10240 + so, qkvl + g);
                CP_ASYNC16(nb + 20480 + so, qkvh + g + 256);
                CP_ASYNC16(nb + 30720 + so, qkvl + g + 256);
            }
            CP_COMMIT();
        }

#pragma unroll
        for (int hf = 0; hf < 2; ++hf) {
            const uint32_t hof = (uint32_t)(hf * 64 * PITCH) * 2;   // 5120
            const uint32_t uKh = bufb + hof, uKl = bufb + 10240 + hof;
            const uint32_t uVh = bufb + 20480 + hof, uVl = bufb + 30720 + hof;
            const int kt = ko * 2 + hf;

            // ---- S = Q K^T (3-term split) ----
            float sacc[8][4];
#pragma unroll
            for (int nt = 0; nt < 8; ++nt)
#pragma unroll
                for (int i = 0; i < 4; ++i) sacc[nt][i] = 0.0f;

#pragma unroll
            for (int kk = 0; kk < 2; ++kk) {
                const uint32_t kof = (uint32_t)(kk * 16) * 2;
                uint32_t bh[4][4], bl[4][4];
#pragma unroll
                for (int ntp = 0; ntp < 4; ++ntp) {
                    uint32_t ba = koff + (uint32_t)(ntp * 16 * PITCH) * 2 + kof;
                    LDSM_X4(bh[ntp][0], bh[ntp][1], bh[ntp][2], bh[ntp][3], uKh + ba);
                    LDSM_X4(bl[ntp][0], bl[ntp][1], bl[ntp][2], bl[ntp][3], uKl + ba);
                }
#pragma unroll
                for (int nt = 0; nt < 8; ++nt) {
                    const int ntp = nt >> 1;
                    const int hb = (nt & 1) * 2;
                    MMA_BF16(sacc[nt], qh[kk][0], qh[kk][1], qh[kk][2], qh[kk][3],
                             bh[ntp][hb], bh[ntp][hb + 1]);
                    MMA_BF16(sacc[nt], qh[kk][0], qh[kk][1], qh[kk][2], qh[kk][3],
                             bl[ntp][hb], bl[ntp][hb + 1]);
                    MMA_BF16(sacc[nt], ql[kk][0], ql[kk][1], ql[kk][2], ql[kk][3],
                             bh[ntp][hb], bh[ntp][hb + 1]);
                }
            }

            // ---- scale + bias (log2 domain, coalesced LDG.128) ----
            const float4* bt = bias_tb + kt * 2048;
#pragma unroll
            for (int nt = 0; nt < 8; ++nt) {
                float4 bb = bt[nt * 32];
                sacc[nt][0] = fmaf(sacc[nt][0], scale, bb.x);
                sacc[nt][1] = fmaf(sacc[nt][1], scale, bb.y);
                sacc[nt][2] = fmaf(sacc[nt][2], scale, bb.z);
                sacc[nt][3] = fmaf(sacc[nt][3], scale, bb.w);
            }

            // ---- online softmax (log2 domain) ----
            float mt0 = -1e30f, mt1 = -1e30f;
#pragma unroll
            for (int nt = 0; nt < 8; ++nt) {
                mt0 = fmaxf(mt0, fmaxf(sacc[nt][0], sacc[nt][1]));
                mt1 = fmaxf(mt1, fmaxf(sacc[nt][2], sacc[nt][3]));
            }
            mt0 = fmaxf(mt0, __shfl_xor_sync(0xffffffffu, mt0, 1));
            mt0 = fmaxf(mt0, __shfl_xor_sync(0xffffffffu, mt0, 2));
            mt1 = fmaxf(mt1, __shfl_xor_sync(0xffffffffu, mt1, 1));
            mt1 = fmaxf(mt1, __shfl_xor_sync(0xffffffffu, mt1, 2));
            float mn0 = fmaxf(m0, mt0), mn1 = fmaxf(m1, mt1);
            float sc0 = exp2f(m0 - mn0), sc1 = exp2f(m1 - mn1);
            float rs0 = 0.0f, rs1 = 0.0f;
#pragma unroll
            for (int nt = 0; nt < 8; ++nt) {
                sacc[nt][0] = exp2f(sacc[nt][0] - mn0);
                sacc[nt][1] = exp2f(sacc[nt][1] - mn0);
                sacc[nt][2] = exp2f(sacc[nt][2] - mn1);
                sacc[nt][3] = exp2f(sacc[nt][3] - mn1);
                rs0 += sacc[nt][0] + sacc[nt][1];
                rs1 += sacc[nt][2] + sacc[nt][3];
            }
            rs0 += __shfl_xor_sync(0xffffffffu, rs0, 1);
            rs0 += __shfl_xor_sync(0xffffffffu, rs0, 2);
            rs1 += __shfl_xor_sync(0xffffffffu, rs1, 1);
            rs1 += __shfl_xor_sync(0xffffffffu, rs1, 2);
            l0 = l0 * sc0 + rs0;
            l1 = l1 * sc1 + rs1;
            m0 = mn0; m1 = mn1;
#pragma unroll
            for (int nt = 0; nt < 4; ++nt) {
                oacc[nt][0] *= sc0; oacc[nt][1] *= sc0;
                oacc[nt][2] *= sc1; oacc[nt][3] *= sc1;
            }

            // ---- O += P V ----
#pragma unroll
            for (int ks = 0; ks < 4; ++ks) {
                __nv_bfloat162 hh, ll;
                uint32_t pah[4], pal[4];
                split2(sacc[2 * ks][0],     sacc[2 * ks][1],     hh, ll);
                pah[0] = u32of(hh); pal[0] = u32of(ll);
                split2(sacc[2 * ks][2],     sacc[2 * ks][3],     hh, ll);
                pah[1] = u32of(hh); pal[1] = u32of(ll);
                split2(sacc[2 * ks + 1][0], sacc[2 * ks + 1][1], hh, ll);
                pah[2] = u32of(hh); pal[2] = u32of(ll);
                split2(sacc[2 * ks + 1][2], sacc[2 * ks + 1][3], hh, ll);
                pah[3] = u32of(hh); pal[3] = u32of(ll);

                uint32_t vh[2][4], vl[2][4];
#pragma unroll
                for (int ntp = 0; ntp < 2; ++ntp) {
                    uint32_t va = voff + (uint32_t)(ks * 16 * PITCH + ntp * 16) * 2;
                    LDSM_X4T(vh[ntp][0], vh[ntp][1], vh[ntp][2], vh[ntp][3], uVh + va);
                    LDSM_X4T(vl[ntp][0], vl[ntp][1], vl[ntp][2], vl[ntp][3], uVl + va);
                }
#pragma unroll
                for (int nt = 0; nt < 4; ++nt) {
                    const int ntp = nt >> 1;
                    const int hb = (nt & 1) * 2;
                    MMA_BF16(oacc[nt], pah[0], pah[1], pah[2], pah[3],
                             vh[ntp][hb], vh[ntp][hb + 1]);
                    MMA_BF16(oacc[nt], pah[0], pah[1], pah[2], pah[3],
                             vl[ntp][hb], vl[ntp][hb + 1]);
                    MMA_BF16(oacc[nt], pal[0], pal[1], pal[2], pal[3],
                             vh[ntp][hb], vh[ntp][hb + 1]);
                }
            }
        }

        if (ko < 7) CP_WAIT0();
        __syncthreads();
    }

    // ---- epilogue ----
    const float inv0 = 1.0f / l0;
    const float inv1 = 1.0f / l1;
    const int row0 = qrow0 + w * 16 + gid;
#pragma unroll
    for (int nt = 0; nt < 4; ++nt) {
        int col = h * HD_ + nt * 8 + 2 * tig;
        __nv_bfloat162 hv, lv;
        split2(oacc[nt][0] * inv0, oacc[nt][1] * inv0, hv, lv);
        *reinterpret_cast<uint32_t*>(outh + (size_t)row0 * C_ + col) = u32of(hv);
        *reinterpret_cast<uint32_t*>(outl + (size_t)row0 * C_ + col) = u32of(lv);
        split2(oacc[nt][2] * inv1, oacc[nt][3] * inv1, hv, lv);
        *reinterpret_cast<uint32_t*>(outh + (size_t)(row0 + 8) * C_ + col) = u32of(hv);
        *reinterpret_cast<uint32_t*>(outl + (size_t)(row0 + 8) * C_ + col) = u32of(lv);
    }
}

// ---------------------------------------------------------------------------
// launch
// ---------------------------------------------------------------------------
extern "C" void kernel_launch(void* const* d_in, const int* in_sizes, int n_in,
                              void* d_out, int out_size) {
    const float* x     = (const float*)d_in[0];
    const float* elev  = (const float*)d_in[1];
    const float* uw    = (const float*)d_in[2];
    const float* vw    = (const float*)d_in[3];
    const float* wqkv  = (const float*)d_in[4];
    const float* wproj = (const float*)d_in[5];
    const float* bproj = (const float*)d_in[6];
    const float* alpha = (const float*)d_in[7];
    const float* beta  = (const float*)d_in[8];
    float* out = (float*)d_out;

    float *ws_p;
    float4* bias4_p;
    __nv_bfloat16 *xh, *xl, *wqkvh, *wqkvl, *wprojh, *wprojl;
    __nv_bfloat16 *qkvh, *qkvl, *attnh, *attnl;
    cudaGetSymbolAddress((void**)&ws_p, g_ws);
    cudaGetSymbolAddress((void**)&bias4_p, g_bias4);
    cudaGetSymbolAddress((void**)&xh, g_xh);
    cudaGetSymbolAddress((void**)&xl, g_xl);
    cudaGetSymbolAddress((void**)&wqkvh, g_wqkvh);
    cudaGetSymbolAddress((void**)&wqkvl, g_wqkvl);
    cudaGetSymbolAddress((void**)&wprojh, g_wprojh);
    cudaGetSymbolAddress((void**)&wprojl, g_wprojl);
    cudaGetSymbolAddress((void**)&qkvh, g_qkvh);
    cudaGetSymbolAddress((void**)&qkvl, g_qkvl);
    cudaGetSymbolAddress((void**)&attnh, g_attnh);
    cudaGetSymbolAddress((void**)&attnl, g_attnl);

    cudaFuncSetAttribute(gemm_bs<false, true>,
                         cudaFuncAttributeMaxDynamicSharedMemorySize,
                         GEMM_SMEM_BYTES);
    cudaFuncSetAttribute(gemm_bs<true, false>,
                         cudaFuncAttributeMaxDynamicSharedMemorySize,
                         GEMM_SMEM_BYTES);
    cudaFuncSetAttribute(attn_mma,
                         cudaFuncAttributeMaxDynamicSharedMemorySize,
                         ATTN_SMEM_BYTES);

    // 1) merged converts + wind strength (fused)
    convert_all<<<(N4_TOTAL + B_ * N_ + 255) / 256, 256>>>(
        x, wqkv, wproj, uw, vw, xh, xl, wqkvh, wqkvl, wprojh, wprojl, ws_p);

    // 2) fragment-ordered bias (log2-scaled)
    bias_perm_kernel<<<B_ * N_ * N_ / 4 / 256, 256>>>(elev, ws_p, alpha, beta,
                                                      bias4_p);

    // 3) qkv = x @ w_qkv^T (split output)
    gemm_bs<false, true><<<dim3(6, 64), 256, GEMM_SMEM_BYTES>>>(
        xh, xl, wqkvh, wqkvl, nullptr, nullptr, qkvh, qkvl, 768);

    // 4) flash attention (split output)
    attn_mma<<<dim3(8, NH_, B_), 256, ATTN_SMEM_BYTES>>>(
        qkvh, qkvl, bias4_p, attnh, attnl);

    // 5) out = attn @ w_proj^T + b_proj (f32 output)
    gemm_bs<true, false><<<dim3(2, 64), 256, GEMM_SMEM_BYTES>>>(
        attnh, attnl, wprojh, wprojl, bproj, out, nullptr, nullptr, 256);
}

// round 10
// speedup vs baseline: 1.1023x; 1.1023x over previous
#include <cuda_runtime.h>
#include <cuda_bf16.h>
#include <math.h>
#include <cstdint>

// ---------------------------------------------------------------------------
// PhysicsGuidedAttentionCorrected
// B=8, N=1024, C=256, NUM_HEADS=8, hd=32
// R10: R8 base (64-key double-buffer, natural-domain __expf) +
//      (1) no online max — softmax shift-invariance + bounded S removes the
//          per-tile warp-wide max/rescale chain; l reduced once at the end.
//      (2) proj GEMM on 64x128 tiles (256 CTAs -> full first wave).
// ---------------------------------------------------------------------------

#define B_ 8
#define N_ 1024
#define C_ 256
#define NH_ 8
#define HD_ 32

// scratch (device globals; no allocations allowed)
__device__ float g_ws[B_ * N_];
__device__ float4 g_bias4[B_ * N_ * N_ / 4];       // fragment-ordered bias
__device__ __nv_bfloat16 g_xh[B_ * N_ * C_];
__device__ __nv_bfloat16 g_xl[B_ * N_ * C_];
__device__ __nv_bfloat16 g_wqkvh[3 * C_ * C_];
__device__ __nv_bfloat16 g_wqkvl[3 * C_ * C_];
__device__ __nv_bfloat16 g_wprojh[C_ * C_];
__device__ __nv_bfloat16 g_wprojl[C_ * C_];
__device__ __nv_bfloat16 g_qkvh[B_ * N_ * 3 * C_];
__device__ __nv_bfloat16 g_qkvl[B_ * N_ * 3 * C_];
__device__ __nv_bfloat16 g_attnh[B_ * N_ * C_];
__device__ __nv_bfloat16 g_attnl[B_ * N_ * C_];

// ---------------------------------------------------------------------------
// helpers
// ---------------------------------------------------------------------------
__device__ __forceinline__ uint32_t smem_u32(const void* p) {
    uint32_t a;
    asm("{ .reg .u64 t; cvta.to.shared.u64 t, %1; cvt.u32.u64 %0, t; }"
        : "=r"(a) : "l"(p));
    return a;
}

#define LDSM_X4(r0, r1, r2, r3, addr)                                        \
    asm volatile("ldmatrix.sync.aligned.m8n8.x4.shared.b16 {%0,%1,%2,%3}, [%4];" \
                 : "=r"(r0), "=r"(r1), "=r"(r2), "=r"(r3) : "r"(addr))

#define LDSM_X4T(r0, r1, r2, r3, addr)                                       \
    asm volatile("ldmatrix.sync.aligned.m8n8.x4.trans.shared.b16 {%0,%1,%2,%3}, [%4];" \
                 : "=r"(r0), "=r"(r1), "=r"(r2), "=r"(r3) : "r"(addr))

#define MMA_BF16(d, a0, a1, a2, a3, b0, b1)                                  \
    asm volatile("mma.sync.aligned.m16n8k16.row.col.f32.bf16.bf16.f32 "      \
                 "{%0,%1,%2,%3}, {%4,%5,%6,%7}, {%8,%9}, {%0,%1,%2,%3};"     \
                 : "+f"((d)[0]), "+f"((d)[1]), "+f"((d)[2]), "+f"((d)[3])    \
                 : "r"(a0), "r"(a1), "r"(a2), "r"(a3), "r"(b0), "r"(b1))

#define CP_ASYNC16(saddr, gptr)                                              \
    asm volatile("cp.async.cg.shared.global [%0], [%1], 16;"                 \
                 :: "r"(saddr), "l"(gptr))
#define CP_COMMIT() asm volatile("cp.async.commit_group;" ::: "memory")
#define CP_WAIT0()  asm volatile("cp.async.wait_group 0;" ::: "memory")

__device__ __forceinline__ void split2(float x, float y,
                                       __nv_bfloat162& hi, __nv_bfloat162& lo) {
    __nv_bfloat16 hx = __float2bfloat16_rn(x);
    __nv_bfloat16 hy = __float2bfloat16_rn(y);
    hi = __nv_bfloat162(hx, hy);
    lo = __nv_bfloat162(__float2bfloat16_rn(x - __bfloat162float(hx)),
                        __float2bfloat16_rn(y - __bfloat162float(hy)));
}
__device__ __forceinline__ uint32_t u32of(__nv_bfloat162 v) {
    return *reinterpret_cast<uint32_t*>(&v);
}

// ---------------------------------------------------------------------------
// bias precompute in MMA-fragment order (natural domain).
// ---------------------------------------------------------------------------
__device__ __forceinline__ float bias_val(float ei, float wi, float ej,
                                          float wj, float alpha, float beta) {
    float ed = fmaxf((ej - ei) * 1e-3f, 0.0f);
    float z = (wi + wj) * 0.5f - 5.0f;
    float wf = 1.0f / (1.0f + __expf(-z));
    float bia = -alpha * ed * (1.0f - beta * wf);
    return fminf(fmaxf(bia, -10.0f), 0.0f);
}

__global__ __launch_bounds__(256)
void bias_perm_kernel(const float* __restrict__ elev, const float* __restrict__ ws,
                      const float* __restrict__ alpha_p,
                      const float* __restrict__ beta_p,
                      float4* __restrict__ bias4) {
    const int t = blockIdx.x * blockDim.x + threadIdx.x;
    const int lane = t & 31;
    const int nt = (t >> 5) & 7;
    const int w  = (t >> 8) & 7;
    const int kt = (t >> 11) & 15;
    const int qt = (t >> 15) & 7;
    const int b  = t >> 18;
    const float alpha = *alpha_p;
    const float beta = *beta_p;

    const int i0 = qt * 128 + w * 16 + (lane >> 2);
    const int j0 = kt * 64 + nt * 8 + 2 * (lane & 3);
    const float* e = elev + b * 1024;
    const float* wsb = ws + b * 1024;
    float ei0 = e[i0], ei1 = e[i0 + 8];
    float wi0 = wsb[i0], wi1 = wsb[i0 + 8];
    float ej0 = e[j0], ej1 = e[j0 + 1];
    float wj0 = wsb[j0], wj1 = wsb[j0 + 1];

    float4 o;
    o.x = bias_val(ei0, wi0, ej0, wj0, alpha, beta);
    o.y = bias_val(ei0, wi0, ej1, wj1, alpha, beta);
    o.z = bias_val(ei1, wi1, ej0, wj0, alpha, beta);
    o.w = bias_val(ei1, wi1, ej1, wj1, alpha, beta);
    bias4[t] = o;
}

// ---------------------------------------------------------------------------
// merged converter (x | wqkv | wproj) + fused wind strength
// ---------------------------------------------------------------------------
#define N4_X (B_ * N_ * C_ / 4)
#define N4_WQKV (3 * C_ * C_ / 4)
#define N4_WPROJ (C_ * C_ / 4)
#define N4_TOTAL (N4_X + N4_WQKV + N4_WPROJ)

__global__ void convert_all(const float* __restrict__ x,
                            const float* __restrict__ wqkv,
                            const float* __restrict__ wproj,
                            const float* __restrict__ uwind,
                            const float* __restrict__ vwind,
                            __nv_bfloat16* __restrict__ xh, __nv_bfloat16* __restrict__ xl,
                            __nv_bfloat16* __restrict__ wqh, __nv_bfloat16* __restrict__ wql,
                            __nv_bfloat16* __restrict__ wph, __nv_bfloat16* __restrict__ wpl,
                            float* __restrict__ ws) {
    int i = blockIdx.x * blockDim.x + threadIdx.x;
    if (i >= N4_TOTAL) {
        int t = i - N4_TOTAL;
        if (t >= B_ * N_) return;
        int b = t >> 10;
        int n = t & 1023;
        int r = n >> 5;
        int c = n & 31;
        const float* ub = uwind + b * 4096;
        const float* vb = vwind + b * 4096;
        float s = 0.0f;
#pragma unroll
        for (int dr = 0; dr < 2; ++dr)
#pragma unroll
            for (int dc = 0; dc < 2; ++dc) {
                int idx = (2 * r + dr) * 64 + (2 * c + dc);
                float uu = ub[idx], vv = vb[idx];
                s += sqrtf(uu * uu + vv * vv + 1e-8f);
            }
        ws[t] = s * 0.25f;
        return;
    }
    const float* in;
    __nv_bfloat16 *hi, *lo;
    int off;
    if (i < N4_X) { in = x; hi = xh; lo = xl; off = i; }
    else if (i < N4_X + N4_WQKV) { in = wqkv; hi = wqh; lo = wql; off = i - N4_X; }
    else { in = wproj; hi = wph; lo = wpl; off = i - N4_X - N4_WQKV; }
    float4 v = reinterpret_cast<const float4*>(in)[off];
    __nv_bfloat162 h01, l01, h23, l23;
    split2(v.x, v.y, h01, l01);
    split2(v.z, v.w, h23, l23);
    uint2 hv = make_uint2(u32of(h01), u32of(h23));
    uint2 lv = make_uint2(u32of(l01), u32of(l23));
    *reinterpret_cast<uint2*>(hi + 4 * off) = hv;
    *reinterpret_cast<uint2*>(lo + 4 * off) = lv;
}

// ---------------------------------------------------------------------------
// bf16-split tensor-core GEMM 128x128, cp.async double-buffered (proven).
// Used for QKV (split output).
// ---------------------------------------------------------------------------
#define PITCH 40
#define GEMM_BUF_BYTES (4 * 128 * PITCH * 2)
#define GEMM_SMEM_BYTES (2 * GEMM_BUF_BYTES)

__global__ __launch_bounds__(256, 2)
void gemm_qkv(const __nv_bfloat16* __restrict__ Ah, const __nv_bfloat16* __restrict__ Al,
              const __nv_bfloat16* __restrict__ Bh, const __nv_bfloat16* __restrict__ Bl,
              __nv_bfloat16* __restrict__ Ch, __nv_bfloat16* __restrict__ Cl) {
    const int N = 768;
    extern __shared__ __align__(16) char smem_raw[];
    const uint32_t uS = smem_u32(smem_raw);

    const int tid = threadIdx.x;
    const int lane = tid & 31;
    const int wid = tid >> 5;
    const int wm = wid & 1;
    const int wn = wid >> 1;
    const int bx = blockIdx.x;
    const int by = blockIdx.y;

    const __nv_bfloat16* Agh = Ah + (size_t)by * 128 * 256;
    const __nv_bfloat16* Agl = Al + (size_t)by * 128 * 256;
    const __nv_bfloat16* Bgh = Bh + (size_t)bx * 128 * 256;
    const __nv_bfloat16* Bgl = Bl + (size_t)bx * 128 * 256;

    float acc[4][4][4];
#pragma unroll
    for (int mt = 0; mt < 4; ++mt)
#pragma unroll
        for (int nt = 0; nt < 4; ++nt)
#pragma unroll
            for (int i = 0; i < 4; ++i) acc[mt][nt][i] = 0.0f;

    const uint32_t aoff =
        (uint32_t)((wm * 64 + (lane & 15)) * PITCH + ((lane & 16) ? 8 : 0)) * 2;
    const uint32_t boff =
        (uint32_t)((wn * 32 + (lane & 7) + ((lane & 16) ? 8 : 0)) * PITCH +
                   ((lane & 8) ? 8 : 0)) * 2;

    const int row0 = tid >> 2;
    const int c8 = (tid & 3) * 8;

#pragma unroll
    for (int i = 0; i < 2; ++i) {
        int row = row0 + i * 64;
        size_t g = (size_t)row * 256 + c8;
        uint32_t so = (uint32_t)(row * PITCH + c8) * 2;
        CP_ASYNC16(uS + so, Agh + g);
        CP_ASYNC16(uS + 10240 + so, Agl + g);
        CP_ASYNC16(uS + 20480 + so, Bgh + g);
        CP_ASYNC16(uS + 30720 + so, Bgl + g);
    }
    CP_COMMIT();
    CP_WAIT0();
    __syncthreads();

#pragma unroll 1
    for (int kb = 0; kb < 8; ++kb) {
        const int p = kb & 1;
        const uint32_t bufb = uS + (uint32_t)p * GEMM_BUF_BYTES;

        if (kb < 7) {
            const uint32_t nb = uS + (uint32_t)(1 - p) * GEMM_BUF_BYTES;
#pragma unroll
            for (int i = 0; i < 2; ++i) {
                int row = row0 + i * 64;
                size_t g = (size_t)row * 256 + (kb + 1) * 32 + c8;
                uint32_t so = (uint32_t)(row * PITCH + c8) * 2;
                CP_ASYNC16(nb + so, Agh + g);
                CP_ASYNC16(nb + 10240 + so, Agl + g);
                CP_ASYNC16(nb + 20480 + so, Bgh + g);
                CP_ASYNC16(nb + 30720 + so, Bgl + g);
            }
            CP_COMMIT();
        }

        const uint32_t uAh = bufb, uAl = bufb + 10240;
        const uint32_t uBh = bufb + 20480, uBl = bufb + 30720;

#pragma unroll
        for (int kk = 0; kk < 2; ++kk) {
            const uint32_t kof = (uint32_t)(kk * 16) * 2;
            uint32_t bhf[2][4], blf[2][4];
#pragma unroll
            for (int ntp = 0; ntp < 2; ++ntp) {
                uint32_t ba = boff + (uint32_t)(ntp * 16 * PITCH) * 2 + kof;
                LDSM_X4(bhf[ntp][0], bhf[ntp][1], bhf[ntp][2], bhf[ntp][3], uBh + ba);
                LDSM_X4(blf[ntp][0], blf[ntp][1], blf[ntp][2], blf[ntp][3], uBl + ba);
            }
#pragma unroll
            for (int mt = 0; mt < 4; ++mt) {
                uint32_t aa = aoff + (uint32_t)(mt * 16 * PITCH) * 2 + kof;
                uint32_t ah0, ah1, ah2, ah3, al0, al1, al2, al3;
                LDSM_X4(ah0, ah1, ah2, ah3, uAh + aa);
                LDSM_X4(al0, al1, al2, al3, uAl + aa);
#pragma unroll
                for (int nt = 0; nt < 4; ++nt) {
                    const int ntp = nt >> 1;
                    const int hb = (nt & 1) * 2;
                    MMA_BF16(acc[mt][nt], ah0, ah1, ah2, ah3,
                             bhf[ntp][hb], bhf[ntp][hb + 1]);
                    MMA_BF16(acc[mt][nt], ah0, ah1, ah2, ah3,
                             blf[ntp][hb], blf[ntp][hb + 1]);
                    MMA_BF16(acc[mt][nt], al0, al1, al2, al3,
                             bhf[ntp][hb], bhf[ntp][hb + 1]);
                }
            }
        }

        if (kb < 7) CP_WAIT0();
        __syncthreads();
    }

    const int gid = lane >> 2;
    const int tig = lane & 3;
#pragma unroll
    for (int mt = 0; mt < 4; ++mt) {
        int row = by * 128 + wm * 64 + mt * 16 + gid;
#pragma unroll
        for (int nt = 0; nt < 4; ++nt) {
            int col = bx * 128 + wn * 32 + nt * 8 + 2 * tig;
            __nv_bfloat162 hh, ll;
            split2(acc[mt][nt][0], acc[mt][nt][1], hh, ll);
            *reinterpret_cast<uint32_t*>(Ch + (size_t)row * N + col) = u32of(hh);
            *reinterpret_cast<uint32_t*>(Cl + (size_t)row * N + col) = u32of(ll);
            split2(acc[mt][nt][2], acc[mt][nt][3], hh, ll);
            *reinterpret_cast<uint32_t*>(Ch + (size_t)(row + 8) * N + col) = u32of(hh);
            *reinterpret_cast<uint32_t*>(Cl + (size_t)(row + 8) * N + col) = u32of(ll);
        }
    }
}

// ---------------------------------------------------------------------------
// proj GEMM: 64x128 tiles (256 CTAs -> full wave), f32 + bias output.
// 8 warps: wm = wid&1 (32-row half), wn = wid>>1 (32-col block).
// ---------------------------------------------------------------------------
#define P64_BUF_BYTES (2 * 64 * PITCH * 2 + 2 * 128 * PITCH * 2)   // 30720
#define P64_SMEM_BYTES (2 * P64_BUF_BYTES)                          // 61440

__global__ __launch_bounds__(256, 2)
void gemm_proj(const __nv_bfloat16* __restrict__ Ah, const __nv_bfloat16* __restrict__ Al,
               const __nv_bfloat16* __restrict__ Bh, const __nv_bfloat16* __restrict__ Bl,
               const float* __restrict__ bias, float* __restrict__ C) {
    const int N = 256;
    extern __shared__ __align__(16) char smem_raw[];
    const uint32_t uS = smem_u32(smem_raw);

    const int tid = threadIdx.x;
    const int lane = tid & 31;
    const int wid = tid >> 5;
    const int wm = wid & 1;
    const int wn = wid >> 1;
    const int bx = blockIdx.x;   // 0..1 (N tiles)
    const int by = blockIdx.y;   // 0..127 (M tiles of 64)

    const __nv_bfloat16* Agh = Ah + (size_t)by * 64 * 256;
    const __nv_bfloat16* Agl = Al + (size_t)by * 64 * 256;
    const __nv_bfloat16* Bgh = Bh + (size_t)bx * 128 * 256;
    const __nv_bfloat16* Bgl = Bl + (size_t)bx * 128 * 256;

    float acc[2][4][4];
#pragma unroll
    for (int mt = 0; mt < 2; ++mt)
#pragma unroll
        for (int nt = 0; nt < 4; ++nt)
#pragma unroll
            for (int i = 0; i < 4; ++i) acc[mt][nt][i] = 0.0f;

    const uint32_t aoff =
        (uint32_t)((wm * 32 + (lane & 15)) * PITCH + ((lane & 16) ? 8 : 0)) * 2;
    const uint32_t boff =
        (uint32_t)((wn * 32 + (lane & 7) + ((lane & 16) ? 8 : 0)) * PITCH +
                   ((lane & 8) ? 8 : 0)) * 2;

    // staging: A 64x(32) = 256 chunks (1/thread); B 128x(32) = 512 (2/thread)
    const int arow = tid >> 2;           // 0..63
    const int ac8 = (tid & 3) * 8;
    const uint32_t aso = (uint32_t)(arow * PITCH + ac8) * 2;
    const int brow0 = tid >> 2;
    // B smem offsets inside stage: Bh at 10240, Bl at 20480

#pragma unroll 1
    for (int kb = -1; kb < 8; ++kb) {
        // prefetch kb+1 (kb=-1 is prologue)
        if (kb < 7) {
            const uint32_t nb = uS + (uint32_t)((kb + 1) & 1) * P64_BUF_BYTES;
            int kof = (kb + 1) * 32;
            {
                size_t g = (size_t)arow * 256 + kof + ac8;
                CP_ASYNC16(nb + aso, Agh + g);
                CP_ASYNC16(nb + 5120 + aso, Agl + g);
            }
#pragma unroll
            for (int i = 0; i < 2; ++i) {
                int row = brow0 + i * 64;
                size_t g = (size_t)row * 256 + kof + ac8;
                uint32_t so = (uint32_t)(row * PITCH + ac8) * 2;
                CP_ASYNC16(nb + 10240 + so, Bgh + g);
                CP_ASYNC16(nb + 20480 + so, Bgl + g);
            }
            CP_COMMIT();
        }
        if (kb < 0) { CP_WAIT0(); __syncthreads(); continue; }

        const uint32_t bufb = uS + (uint32_t)(kb & 1) * P64_BUF_BYTES;
        const uint32_t uAh = bufb, uAl = bufb + 5120;
        const uint32_t uBh = bufb + 10240, uBl = bufb + 20480;

#pragma unroll
        for (int kk = 0; kk < 2; ++kk) {
            const uint32_t kof = (uint32_t)(kk * 16) * 2;
            uint32_t bhf[2][4], blf[2][4];
#pragma unroll
            for (int ntp = 0; ntp < 2; ++ntp) {
                uint32_t ba = boff + (uint32_t)(ntp * 16 * PITCH) * 2 + kof;
                LDSM_X4(bhf[ntp][0], bhf[ntp][1], bhf[ntp][2], bhf[ntp][3], uBh + ba);
                LDSM_X4(blf[ntp][0], blf[ntp][1], blf[ntp][2], blf[ntp][3], uBl + ba);
            }
#pragma unroll
            for (int mt = 0; mt < 2; ++mt) {
                uint32_t aa = aoff + (uint32_t)(mt * 16 * PITCH) * 2 + kof;
                uint32_t ah0, ah1, ah2, ah3, al0, al1, al2, al3;
                LDSM_X4(ah0, ah1, ah2, ah3, uAh + aa);
                LDSM_X4(al0, al1, al2, al3, uAl + aa);
#pragma unroll
                for (int nt = 0; nt < 4; ++nt) {
                    const int ntp = nt >> 1;
                    const int hb = (nt & 1) * 2;
                    MMA_BF16(acc[mt][nt], ah0, ah1, ah2, ah3,
                             bhf[ntp][hb], bhf[ntp][hb + 1]);
                    MMA_BF16(acc[mt][nt], ah0, ah1, ah2, ah3,
                             blf[ntp][hb], blf[ntp][hb + 1]);
                    MMA_BF16(acc[mt][nt], al0, al1, al2, al3,
                             bhf[ntp][hb], bhf[ntp][hb + 1]);
                }
            }
        }

        if (kb < 7) CP_WAIT0();
        __syncthreads();
    }

    const int gid = lane >> 2;
    const int tig = lane & 3;
#pragma unroll
    for (int mt = 0; mt < 2; ++mt) {
        int row = by * 64 + wm * 32 + mt * 16 + gid;
#pragma unroll
        for (int nt = 0; nt < 4; ++nt) {
            int col = bx * 128 + wn * 32 + nt * 8 + 2 * tig;
            float2 bb = *reinterpret_cast<const float2*>(bias + col);
            float2 v0 = make_float2(acc[mt][nt][0] + bb.x, acc[mt][nt][1] + bb.y);
            float2 v1 = make_float2(acc[mt][nt][2] + bb.x, acc[mt][nt][3] + bb.y);
            *reinterpret_cast<float2*>(C + (size_t)row * N + col) = v0;
            *reinterpret_cast<float2*>(C + (size_t)(row + 8) * N + col) = v1;
        }
    }
}

// ---------------------------------------------------------------------------
// tensor-core flash attention (R8 structure), NO online max:
// S*scale+bias is bounded (|s|~<6, bias<=0) so raw __expf is safe; softmax is
// shift-invariant. l accumulates per-thread, one shuffle reduce at the end.
// ---------------------------------------------------------------------------
#define ATTN_Q_BYTES (2 * 128 * PITCH * 2)
#define ATTN_BUF_BYTES (4 * 64 * PITCH * 2)
#define ATTN_SMEM_BYTES (ATTN_Q_BYTES + 2 * ATTN_BUF_BYTES)

__global__ __launch_bounds__(256, 2)
void attn_mma(const __nv_bfloat16* __restrict__ qkvh,
              const __nv_bfloat16* __restrict__ qkvl,
              const float4* __restrict__ bias4,
              __nv_bfloat16* __restrict__ outh,
              __nv_bfloat16* __restrict__ outl) {
    extern __shared__ __align__(16) char smem_raw[];
    __nv_bfloat16* Qh = reinterpret_cast<__nv_bfloat16*>(smem_raw);
    __nv_bfloat16* Ql = Qh + 128 * PITCH;
    const uint32_t uQh = smem_u32(Qh);
    const uint32_t uQl = uQh + 128 * PITCH * 2;
    const uint32_t uKV = uQl + 128 * PITCH * 2;

    const int tid = threadIdx.x;
    const int lane = tid & 31;
    const int w = tid >> 5;
    const int gid = lane >> 2;
    const int tig = lane & 3;
    const int qc = blockIdx.x;
    const int h  = blockIdx.y;
    const int b  = blockIdx.z;

    const float scale = 0.17677669529663687f;   // 1/sqrt(32)
    const int qrow0 = b * N_ + qc * 128;

    const int krow = tid >> 2;
    const int kc8 = (tid & 3) * 8;
    const uint32_t kso = (uint32_t)(krow * PITCH + kc8) * 2;

    // prologue: stage kt=0 into buffer 0
    {
        size_t g = (size_t)(b * N_ + krow) * 768 + 256 + h * HD_ + kc8;
        CP_ASYNC16(uKV + kso, qkvh + g);
        CP_ASYNC16(uKV + 5120 + kso, qkvl + g);
        CP_ASYNC16(uKV + 10240 + kso, qkvh + g + 256);
        CP_ASYNC16(uKV + 15360 + kso, qkvl + g + 256);
        CP_COMMIT();
    }

    // stage Q
#pragma unroll
    for (int i = 0; i < 2; ++i) {
        int slot = tid + i * 256;
        int row = slot >> 2;
        int c8 = (slot & 3) * 8;
        size_t g = (size_t)(qrow0 + row) * 768 + h * HD_ + c8;
        int so = row * PITCH + c8;
        *reinterpret_cast<uint4*>(&Qh[so]) =
            *reinterpret_cast<const uint4*>(qkvh + g);
        *reinterpret_cast<uint4*>(&Ql[so]) =
            *reinterpret_cast<const uint4*>(qkvl + g);
    }
    CP_WAIT0();
    __syncthreads();

    const uint32_t aoff =
        (uint32_t)((w * 16 + (lane & 15)) * PITCH + ((lane & 16) ? 8 : 0)) * 2;
    const uint32_t koff =
        (uint32_t)(((lane & 7) + ((lane & 16) ? 8 : 0)) * PITCH +
                   ((lane & 8) ? 8 : 0)) * 2;
    const uint32_t voff =
        (uint32_t)((lane & 15) * PITCH + ((lane & 16) ? 8 : 0)) * 2;

    // hoisted Q fragments
    uint32_t qh[2][4], ql[2][4];
#pragma unroll
    for (int kk = 0; kk < 2; ++kk) {
        const uint32_t kof = (uint32_t)(kk * 16) * 2;
        LDSM_X4(qh[kk][0], qh[kk][1], qh[kk][2], qh[kk][3], uQh + aoff + kof);
        LDSM_X4(ql[kk][0], ql[kk][1], ql[kk][2], ql[kk][3], uQl + aoff + kof);
    }

    float l0 = 0.0f, l1 = 0.0f;
    float oacc[4][4];
#pragma unroll
    for (int nt = 0; nt < 4; ++nt)
#pragma unroll
        for (int i = 0; i < 4; ++i) oacc[nt][i] = 0.0f;

    const float4* bias_tb =
        bias4 + ((size_t)((b * 8 + qc) * 16)) * 2048 + (w * 8) * 32 + lane;

#pragma unroll 1
    for (int kt = 0; kt < 16; ++kt) {
        const int p = kt & 1;
        const uint32_t bufb = uKV + (uint32_t)p * ATTN_BUF_BYTES;

        if (kt < 15) {
            const uint32_t nb = uKV + (uint32_t)(1 - p) * ATTN_BUF_BYTES;
            size_t g = (size_t)(b * N_ + (kt + 1) * 64 + krow) * 768 + 256 +
                       h * HD_ + kc8;
            CP_ASYNC16(nb + kso, qkvh + g);
            CP_ASYNC16(nb + 5120 + kso, qkvl + g);
            CP_ASYNC16(nb + 10240 + kso, qkvh + g + 256);
            CP_ASYNC16(nb + 15360 + kso, qkvl + g + 256);
            CP_COMMIT();
        }

        const uint32_t uKh = bufb, uKl = bufb + 5120;
        const uint32_t uVh = bufb + 10240, uVl = bufb + 15360;

        // ---- S = Q K^T (3-term split) ----
        float sacc[8][4];
#pragma unroll
        for (int nt = 0; nt < 8; ++nt)
#pragma unroll
            for (int i = 0; i < 4; ++i) sacc[nt][i] = 0.0f;

#pragma unroll
        for (int kk = 0; kk < 2; ++kk) {
            const uint32_t kof = (uint32_t)(kk * 16) * 2;
            uint32_t bh[4][4], bl[4][4];
#pragma unroll
            for (int ntp = 0; ntp < 4; ++ntp) {
                uint32_t ba = koff + (uint32_t)(ntp * 16 * PITCH) * 2 + kof;
                LDSM_X4(bh[ntp][0], bh[ntp][1], bh[ntp][2], bh[ntp][3], uKh + ba);
                LDSM_X4(bl[ntp][0], bl[ntp][1], bl[ntp][2], bl[ntp][3], uKl + ba);
            }
#pragma unroll
            for (int nt = 0; nt < 8; ++nt) {
                const int ntp = nt >> 1;
                const int hb = (nt & 1) * 2;
                MMA_BF16(sacc[nt], qh[kk][0], qh[kk][1], qh[kk][2], qh[kk][3],
                         bh[ntp][hb], bh[ntp][hb + 1]);
                MMA_BF16(sacc[nt], qh[kk][0], qh[kk][1], qh[kk][2], qh[kk][3],
                         bl[ntp][hb], bl[ntp][hb + 1]);
                MMA_BF16(sacc[nt], ql[kk][0], ql[kk][1], ql[kk][2], ql[kk][3],
                         bh[ntp][hb], bh[ntp][hb + 1]);
            }
        }

        // ---- scale + bias + exp (no max shift; bounded inputs) ----
        const float4* bt = bias_tb + kt * 2048;
#pragma unroll
        for (int nt = 0; nt < 8; ++nt) {
            float4 bb = bt[nt * 32];
            float p0 = __expf(fmaf(sacc[nt][0], scale, bb.x));
            float p1 = __expf(fmaf(sacc[nt][1], scale, bb.y));
            float p2 = __expf(fmaf(sacc[nt][2], scale, bb.z));
            float p3 = __expf(fmaf(sacc[nt][3], scale, bb.w));
            sacc[nt][0] = p0; sacc[nt][1] = p1;
            sacc[nt][2] = p2; sacc[nt][3] = p3;
            l0 += p0 + p1;
            l1 += p2 + p3;
        }

        // ---- O += P V ----
#pragma unroll
        for (int ks = 0; ks < 4; ++ks) {
            __nv_bfloat162 hh, ll;
            uint32_t pah[4], pal[4];
            split2(sacc[2 * ks][0],     sacc[2 * ks][1],     hh, ll);
            pah[0] = u32of(hh); pal[0] = u32of(ll);
            split2(sacc[2 * ks][2],     sacc[2 * ks][3],     hh, ll);
            pah[1] = u32of(hh); pal[1] = u32of(ll);
            split2(sacc[2 * ks + 1][0], sacc[2 * ks + 1][1], hh, ll);
            pah[2] = u32of(hh); pal[2] = u32of(ll);
            split2(sacc[2 * ks + 1][2], sacc[2 * ks + 1][3], hh, ll);
            pah[3] = u32of(hh); pal[3] = u32of(ll);

            uint32_t vh[2][4], vl[2][4];
#pragma unroll
            for (int ntp = 0; ntp < 2; ++ntp) {
                uint32_t va = voff + (uint32_t)(ks * 16 * PITCH + ntp * 16) * 2;
                LDSM_X4T(vh[ntp][0], vh[ntp][1], vh[ntp][2], vh[ntp][3], uVh + va);
                LDSM_X4T(vl[ntp][0], vl[ntp][1], vl[ntp][2], vl[ntp][3], uVl + va);
            }
#pragma unroll
            for (int nt = 0; nt < 4; ++nt) {
                const int ntp = nt >> 1;
                const int hb = (nt & 1) * 2;
                MMA_BF16(oacc[nt], pah[0], pah[1], pah[2], pah[3],
                         vh[ntp][hb], vh[ntp][hb + 1]);
                MMA_BF16(oacc[nt], pah[0], pah[1], pah[2], pah[3],
                         vl[ntp][hb], vl[ntp][hb + 1]);
                MMA_BF16(oacc[nt], pal[0], pal[1], pal[2], pal[3],
                         vh[ntp][hb], vh[ntp][hb + 1]);
            }
        }

        if (kt < 15) CP_WAIT0();
        __syncthreads();
    }

    // ---- one-time l reduction over the 4-lane row group ----
    l0 += __shfl_xor_sync(0xffffffffu, l0, 1);
    l0 += __shfl_xor_sync(0xffffffffu, l0, 2);
    l1 += __shfl_xor_sync(0xffffffffu, l1, 1);
    l1 += __shfl_xor_sync(0xffffffffu, l1, 2);

    // ---- epilogue ----
    const float inv0 = 1.0f / l0;
    const float inv1 = 1.0f / l1;
    const int row0 = qrow0 + w * 16 + gid;
#pragma unroll
    for (int nt = 0; nt < 4; ++nt) {
        int col = h * HD_ + nt * 8 + 2 * tig;
        __nv_bfloat162 hv, lv;
        split2(oacc[nt][0] * inv0, oacc[nt][1] * inv0, hv, lv);
        *reinterpret_cast<uint32_t*>(outh + (size_t)row0 * C_ + col) = u32of(hv);
        *reinterpret_cast<uint32_t*>(outl + (size_t)row0 * C_ + col) = u32of(lv);
        split2(oacc[nt][2] * inv1, oacc[nt][3] * inv1, hv, lv);
        *reinterpret_cast<uint32_t*>(outh + (size_t)(row0 + 8) * C_ + col) = u32of(hv);
        *reinterpret_cast<uint32_t*>(outl + (size_t)(row0 + 8) * C_ + col) = u32of(lv);
    }
}

// ---------------------------------------------------------------------------
// launch
// ---------------------------------------------------------------------------
extern "C" void kernel_launch(void* const* d_in, const int* in_sizes, int n_in,
                              void* d_out, int out_size) {
    const float* x     = (const float*)d_in[0];
    const float* elev  = (const float*)d_in[1];
    const float* uw    = (const float*)d_in[2];
    const float* vw    = (const float*)d_in[3];
    const float* wqkv  = (const float*)d_in[4];
    const float* wproj = (const float*)d_in[5];
    const float* bproj = (const float*)d_in[6];
    const float* alpha = (const float*)d_in[7];
    const float* beta  = (const float*)d_in[8];
    float* out = (float*)d_out;

    float *ws_p;
    float4* bias4_p;
    __nv_bfloat16 *xh, *xl, *wqkvh, *wqkvl, *wprojh, *wprojl;
    __nv_bfloat16 *qkvh, *qkvl, *attnh, *attnl;
    cudaGetSymbolAddress((void**)&ws_p, g_ws);
    cudaGetSymbolAddress((void**)&bias4_p, g_bias4);
    cudaGetSymbolAddress((void**)&xh, g_xh);
    cudaGetSymbolAddress((void**)&xl, g_xl);
    cudaGetSymbolAddress((void**)&wqkvh, g_wqkvh);
    cudaGetSymbolAddress((void**)&wqkvl, g_wqkvl);
    cudaGetSymbolAddress((void**)&wprojh, g_wprojh);
    cudaGetSymbolAddress((void**)&wprojl, g_wprojl);
    cudaGetSymbolAddress((void**)&qkvh, g_qkvh);
    cudaGetSymbolAddress((void**)&qkvl, g_qkvl);
    cudaGetSymbolAddress((void**)&attnh, g_attnh);
    cudaGetSymbolAddress((void**)&attnl, g_attnl);

    cudaFuncSetAttribute(gemm_qkv,
                         cudaFuncAttributeMaxDynamicSharedMemorySize,
                         GEMM_SMEM_BYTES);
    cudaFuncSetAttribute(gemm_proj,
                         cudaFuncAttributeMaxDynamicSharedMemorySize,
                         P64_SMEM_BYTES);
    cudaFuncSetAttribute(attn_mma,
                         cudaFuncAttributeMaxDynamicSharedMemorySize,
                         ATTN_SMEM_BYTES);

    // 1) merged converts + wind strength (fused)
    convert_all<<<(N4_TOTAL + B_ * N_ + 255) / 256, 256>>>(
        x, wqkv, wproj, uw, vw, xh, xl, wqkvh, wqkvl, wprojh, wprojl, ws_p);

    // 2) fragment-ordered bias
    bias_perm_kernel<<<B_ * N_ * N_ / 4 / 256, 256>>>(elev, ws_p, alpha, beta,
                                                      bias4_p);

    // 3) qkv = x @ w_qkv^T (split output)
    gemm_qkv<<<dim3(6, 64), 256, GEMM_SMEM_BYTES>>>(
        xh, xl, wqkvh, wqkvl, qkvh, qkvl);

    // 4) flash attention (split output, no online max)
    attn_mma<<<dim3(8, NH_, B_), 256, ATTN_SMEM_BYTES>>>(
        qkvh, qkvl, bias4_p, attnh, attnl);

    // 5) out = attn @ w_proj^T + b_proj (f32 output, 64-row tiles)
    gemm_proj<<<dim3(2, 128), 256, P64_SMEM_BYTES>>>(
        attnh, attnl, wprojh, wprojl, bproj, out);
}